// round 2
// baseline (speedup 1.0000x reference)
#include <cuda_runtime.h>
#include <cuda_bf16.h>
#include <math_constants.h>

// Problem constants
#define BATCH 64
#define SEQ   256
#define TCH   16
#define VOC   262
#define EMB   64
#define HID   32          // per direction; == warp size
#define G3    96          // 3*HID
#define NSEQ  (BATCH*SEQ) // 16384 words
#define NTASK (NSEQ*2)    // (seq, dir) tasks
#define NJ    16          // HID/2 packed pairs

typedef unsigned long long ull;

// Scratch tables (device globals — no allocation allowed)
__device__ float  g_GIf[VOC * G3];        // bih_f + Wih_f @ emb[c]
__device__ float  g_GIb[VOC * G3];
// Packed recurrent weights: WP[gate][j][lane] = (Whh[gate*32+lane][2j], [2j+1])
__device__ float2 g_WPf[3 * NJ * HID];
__device__ float2 g_WPb[3 * NJ * HID];

__device__ __forceinline__ ull ffma2(ull a, ull b, ull c) {
    ull d;
    asm("fma.rn.f32x2 %0, %1, %2, %3;" : "=l"(d) : "l"(a), "l"(b), "l"(c));
    return d;
}
__device__ __forceinline__ float pairsum(ull v) {
    float lo = __uint_as_float((unsigned)v);
    float hi = __uint_as_float((unsigned)(v >> 32));
    return lo + hi;
}
__device__ __forceinline__ float sigf(float x) {
    return __fdividef(1.0f, 1.0f + __expf(-x));
}
__device__ __forceinline__ float tanhfast(float x) {
    return fmaf(2.0f, sigf(2.0f * x), -1.0f);
}

// ---------------------------------------------------------------------------
// Kernel 1: build GI lookup tables + packed Whh weight tables
// grid = VOC+1 blocks, 96 threads
// ---------------------------------------------------------------------------
__global__ void build_tables(const float* __restrict__ emb,
                             const float* __restrict__ Wih_f,
                             const float* __restrict__ bih_f,
                             const float* __restrict__ Wih_b,
                             const float* __restrict__ bih_b,
                             const float* __restrict__ Whh_f,
                             const float* __restrict__ Whh_b) {
    int c = blockIdx.x;
    int g = threadIdx.x;  // 0..95
    if (c < VOC) {
        __shared__ float e[EMB];
        if (g < EMB) e[g] = emb[c * EMB + g];
        __syncthreads();
        float af = bih_f[g];
        float ab = bih_b[g];
        #pragma unroll
        for (int k = 0; k < EMB; k++) {
            float ev = e[k];
            af = fmaf(Wih_f[g * EMB + k], ev, af);
            ab = fmaf(Wih_b[g * EMB + k], ev, ab);
        }
        g_GIf[c * G3 + g] = af;
        g_GIb[c * G3 + g] = ab;
    } else {
        // pack Whh into float2 pairs: WP[((gate*NJ)+j)*32 + lane]
        for (int i = g; i < 3 * NJ * HID; i += G3) {
            int gate = i / (NJ * HID);
            int rem  = i % (NJ * HID);
            int j    = rem / HID;
            int lane = rem % HID;
            int row  = gate * HID + lane;
            g_WPf[i] = make_float2(Whh_f[row * HID + 2 * j], Whh_f[row * HID + 2 * j + 1]);
            g_WPb[i] = make_float2(Whh_b[row * HID + 2 * j], Whh_b[row * HID + 2 * j + 1]);
        }
    }
}

// ---------------------------------------------------------------------------
// Kernel 2: persistent-warp bidirectional GRU + temporal max-pool.
// One warp per (sequence, direction). Lane l owns h[l].
// h is broadcast via per-warp double-buffered shared memory (LDS.64 pairs);
// recurrent matvec is 48 packed fma.rn.f32x2 per lane per step.
// ---------------------------------------------------------------------------
__global__ __launch_bounds__(256, 2)
void gru_main(const int* __restrict__ x,
              const float* __restrict__ bhh_f,
              const float* __restrict__ bhh_b,
              float* __restrict__ out) {
    __shared__ float shh[8][2][HID];   // [warp-in-block][buf][lane]

    int gtid   = blockIdx.x * blockDim.x + threadIdx.x;
    int w      = gtid >> 5;
    int lane   = gtid & 31;
    int wb     = (threadIdx.x >> 5);
    int nwarps = (gridDim.x * blockDim.x) >> 5;   // even
    int dir    = w & 1;

    const float*  __restrict__ GI  = dir ? g_GIb : g_GIf;
    const float2* __restrict__ WP  = dir ? g_WPb : g_WPf;
    const float*  __restrict__ bhh = dir ? bhh_b : bhh_f;

    // Per-lane packed recurrent weights (loaded once per persistent warp)
    ull wr[NJ], wz[NJ], wn[NJ];
    #pragma unroll
    for (int j = 0; j < NJ; j++) {
        float2 a = WP[(0 * NJ + j) * HID + lane];
        float2 b = WP[(1 * NJ + j) * HID + lane];
        float2 c = WP[(2 * NJ + j) * HID + lane];
        wr[j] = *(ull*)&a;
        wz[j] = *(ull*)&b;
        wn[j] = *(ull*)&c;
    }
    float br = bhh[lane], bz = bhh[32 + lane], bn = bhh[64 + lane];
    ull br2 = (ull)__float_as_uint(br);   // bias in lo half, 0 in hi half
    ull bz2 = (ull)__float_as_uint(bz);
    ull bn2 = (ull)__float_as_uint(bn);

    for (int task = w; task < NTASK; task += nwarps) {
        int seq = task >> 1;   // task&1 == dir (parity preserved)

        int cm = (lane < TCH) ? x[seq * TCH + lane] : 0;

        float h = 0.0f;
        float hmax = -CUDART_INF_F;

        shh[wb][0][lane] = 0.0f;
        __syncwarp();
        int p = 0;

        // prefetch gi for step 0
        int c0 = __shfl_sync(0xffffffffu, cm, dir ? (TCH - 1) : 0);
        const float* gp = GI + c0 * G3 + lane;
        float gir = gp[0], giz = gp[32], gin = gp[64];

        #pragma unroll 1
        for (int tt = 0; tt < TCH; ++tt) {
            // prefetch gi for step tt+1 (last iter: harmless redundant load)
            int tn = (tt + 1) & (TCH - 1);
            int cn = __shfl_sync(0xffffffffu, cm, dir ? (TCH - 1 - tn) : tn);
            const float* gpn = GI + cn * G3 + lane;
            float gir_n = gpn[0], giz_n = gpn[32], gin_n = gpn[64];

            ull ar = br2, az = bz2, an = bn2;
            const ull* hp = (const ull*)&shh[wb][p][0];
            #pragma unroll
            for (int j = 0; j < NJ; j++) {
                ull hv = hp[j];                 // LDS.64, broadcast (N=1)
                ar = ffma2(wr[j], hv, ar);
                az = ffma2(wz[j], hv, az);
                an = ffma2(wn[j], hv, an);
            }
            float ghr = pairsum(ar);
            float ghz = pairsum(az);
            float ghn = pairsum(an);

            float r = sigf(gir + ghr);
            float z = sigf(giz + ghz);
            float n = tanhfast(fmaf(r, ghn, gin));
            h = fmaf(z, h - n, n);              // (1-z)*n + z*h
            hmax = fmaxf(hmax, h);

            shh[wb][p ^ 1][lane] = h;
            __syncwarp();
            p ^= 1;

            gir = gir_n; giz = giz_n; gin = gin_n;
        }

        out[seq * (2 * HID) + dir * HID + lane] = hmax;
    }
}

// ---------------------------------------------------------------------------
// kernel_launch
// inputs: x, emb, Wih_f, Whh_f, bih_f, bhh_f, Wih_b, Whh_b, bih_b, bhh_b
// output: float32 [64, 256, 64]
// ---------------------------------------------------------------------------
extern "C" void kernel_launch(void* const* d_in, const int* in_sizes, int n_in,
                              void* d_out, int out_size) {
    const int*   x     = (const int*)  d_in[0];
    const float* emb   = (const float*)d_in[1];
    const float* Wih_f = (const float*)d_in[2];
    const float* Whh_f = (const float*)d_in[3];
    const float* bih_f = (const float*)d_in[4];
    const float* bhh_f = (const float*)d_in[5];
    const float* Wih_b = (const float*)d_in[6];
    const float* Whh_b = (const float*)d_in[7];
    const float* bih_b = (const float*)d_in[8];
    const float* bhh_b = (const float*)d_in[9];
    float* out = (float*)d_out;

    build_tables<<<VOC + 1, G3>>>(emb, Wih_f, bih_f, Wih_b, bih_b, Whh_f, Whh_b);

    // 296 blocks x 256 threads = 2368 persistent warps (2 CTAs/SM @ 128 regs)
    gru_main<<<296, 256>>>(x, bhh_f, bhh_b, out);
}